// round 5
// baseline (speedup 1.0000x reference)
#include <cuda_runtime.h>
#include <math.h>

#define N       300
#define NM      9
#define BATCH   131072
#define NLAYERS 5
#define KTAP    10
#define TAPS    (2*KTAP + 1)   // 21
#define TBL     416            // table length: lane*13 + t
#define WARPS   16
#define RPW     4              // row-PAIRS per warp
#define LSTRIDE 31             // per-lane float2 slot stride (odd -> conflict-free)
#define WSLOT2  (32 * LSTRIDE) // float2 per warp = 992
#define FULLMASK 0xffffffffu

static __device__ double g_cfull[NLAYERS][N];
static __device__ float  g_G[NLAYERS][NM * N];
static __device__ float  g_At[NM * TBL];             // A[m][j] at [m][13L+t], j=10L+t
static __device__ float  g_Hn[NLAYERS][NM * TBL];    // NEGATED H, same layout
static __device__ float  g_ct[NLAYERS][24];          // conv taps ct[i]=c[|i-10|]
static __device__ float  g_scal[NLAYERS][8];

// ---------------------------------------------------------------------------
// packed f32x2 helpers (sm_103a)
// ---------------------------------------------------------------------------
__device__ __forceinline__ float2 f2fma(float2 a, float2 b, float2 c) {
    unsigned long long ra = reinterpret_cast<unsigned long long&>(a);
    unsigned long long rb = reinterpret_cast<unsigned long long&>(b);
    unsigned long long rc = reinterpret_cast<unsigned long long&>(c);
    unsigned long long rd;
    asm("fma.rn.f32x2 %0, %1, %2, %3;" : "=l"(rd) : "l"(ra), "l"(rb), "l"(rc));
    return reinterpret_cast<float2&>(rd);
}
__device__ __forceinline__ float2 f2add(float2 a, float2 b) {
    unsigned long long ra = reinterpret_cast<unsigned long long&>(a);
    unsigned long long rb = reinterpret_cast<unsigned long long&>(b);
    unsigned long long rd;
    asm("add.rn.f32x2 %0, %1, %2;" : "=l"(rd) : "l"(ra), "l"(rb));
    return reinterpret_cast<float2&>(rd);
}
__device__ __forceinline__ float2 f2mul(float2 a, float2 b) {
    unsigned long long ra = reinterpret_cast<unsigned long long&>(a);
    unsigned long long rb = reinterpret_cast<unsigned long long&>(b);
    unsigned long long rd;
    asm("mul.rn.f32x2 %0, %1, %2;" : "=l"(rd) : "l"(ra), "l"(rb));
    return reinterpret_cast<float2&>(rd);
}
__device__ __forceinline__ float2 dup(float s) { return make_float2(s, s); }
__device__ __forceinline__ float2 shfl2(float2 v, int src) {
    float2 r;
    r.x = __shfl_sync(FULLMASK, v.x, src);
    r.y = __shfl_sync(FULLMASK, v.y, src);
    return r;
}
__device__ __forceinline__ float2 bfly_sum(float2 v) {
    #pragma unroll
    for (int off = 16; off >= 1; off >>= 1) {
        float sx = __shfl_xor_sync(FULLMASK, v.x, off);
        float sy = __shfl_xor_sync(FULLMASK, v.y, off);
        v = f2add(v, make_float2(sx, sy));
    }
    return v;
}
__device__ __forceinline__ float softt(float v, float lam) {
    return copysignf(fmaxf(fabsf(v) - lam, 0.f), v);
}

// ---------------------------------------------------------------------------
__global__ void pre_A_kernel(const float* __restrict__ A) {
    int idx = blockIdx.x * blockDim.x + threadIdx.x;
    if (idx < NM * TBL) {
        int m = idx / TBL, ii = idx % TBL;
        int L = ii / 13, t = ii % 13;
        int j = L * 10 + t;
        g_At[idx] = (t < 10 && j < N) ? A[m * N + j] : 0.0f;
    }
}

// ---------------------------------------------------------------------------
__global__ void pre_layer_kernel(const float* __restrict__ A,
                                 const float* __restrict__ gamma_tv,
                                 const float* __restrict__ lambda_tv,
                                 const float* __restrict__ alpha) {
    const double PI = 3.14159265358979323846;
    int l = blockIdx.x;
    int tid = threadIdx.x;
    double g = (double)gamma_tv[l], al = (double)alpha[l];

    __shared__ double costab[N];
    __shared__ double invlam[N];
    for (int m = tid; m < N; m += blockDim.x) {
        double th = 2.0 * PI * (double)m / (double)N;
        costab[m] = cos(th);
        invlam[m] = 1.0 / (al + 2.0 * g - 2.0 * g * costab[m]);
    }
    __syncthreads();

    for (int k = tid; k < N; k += blockDim.x) {
        double s = 0.0;
        int mk = 0;
        for (int m = 0; m < N; m++) {
            s += costab[mk] * invlam[m];
            mk += k; if (mk >= N) mk -= N;
        }
        g_cfull[l][k] = s / (double)N;
    }
    __syncthreads();

    for (int idx = tid; idx < NM * N; idx += blockDim.x) {
        int m = idx / N, j = idx % N;
        float s = 0.f;
        for (int t = 0; t < N; t++) {
            int d = j - t; if (d < 0) d += N;
            s += A[m * N + t] * (float)g_cfull[l][d];
        }
        g_G[l][m * N + j] = s;
    }
    __syncthreads();

    __shared__ double S9[81], S9i[81];
    for (int idx = tid; idx < 81; idx += blockDim.x) {
        int p = idx / 9, q = idx % 9;
        double s = (p == q) ? 1.0 : 0.0;
        for (int j = 0; j < N; j++)
            s += (double)g_G[l][p * N + j] * (double)A[q * N + j];
        S9[idx] = s;
    }
    __syncthreads();

    if (tid == 0) {
        for (int i = 0; i < 81; i++) S9i[i] = ((i / 9) == (i % 9)) ? 1.0 : 0.0;
        for (int col = 0; col < 9; col++) {
            int piv = col; double best = fabs(S9[col * 9 + col]);
            for (int rr = col + 1; rr < 9; rr++) {
                double v = fabs(S9[rr * 9 + col]);
                if (v > best) { best = v; piv = rr; }
            }
            if (piv != col) {
                for (int c2 = 0; c2 < 9; c2++) {
                    double tmp = S9[col * 9 + c2]; S9[col * 9 + c2] = S9[piv * 9 + c2]; S9[piv * 9 + c2] = tmp;
                    tmp = S9i[col * 9 + c2]; S9i[col * 9 + c2] = S9i[piv * 9 + c2]; S9i[piv * 9 + c2] = tmp;
                }
            }
            double d = 1.0 / S9[col * 9 + col];
            for (int c2 = 0; c2 < 9; c2++) { S9[col * 9 + c2] *= d; S9i[col * 9 + c2] *= d; }
            for (int rr = 0; rr < 9; rr++) {
                if (rr == col) continue;
                double f = S9[rr * 9 + col];
                for (int c2 = 0; c2 < 9; c2++) {
                    S9[rr * 9 + c2]  -= f * S9[col * 9 + c2];
                    S9i[rr * 9 + c2] -= f * S9i[col * 9 + c2];
                }
            }
        }
    }
    __syncthreads();

    for (int idx = tid; idx < NM * TBL; idx += blockDim.x) {
        int m = idx / TBL, ii = idx % TBL;
        int L = ii / 13, t = ii % 13;
        int j = L * 10 + t;
        float s = 0.f;
        if (t < 10 && j < N) {
            for (int q = 0; q < NM; q++)
                s -= (float)S9i[m * 9 + q] * g_G[l][q * N + j];
        }
        g_Hn[l][idx] = s;
    }
    for (int i = tid; i < 24; i += blockDim.x) {
        float v = 0.f;
        if (i < TAPS) { int d = i - KTAP; if (d < 0) d = -d; v = (float)g_cfull[l][d]; }
        g_ct[l][i] = v;
    }
    if (tid == 0) {
        g_scal[l][0] = (float)g;
        g_scal[l][1] = (float)al;
        g_scal[l][2] = (float)((double)lambda_tv[l] / g);
        g_scal[l][3] = (float)(1.0 / g);
        g_scal[l][4] = (float)(1.0 / al);
    }
}

// ---------------------------------------------------------------------------
// Main fused kernel: one warp per PAIR of rows (f32x2), 512-thread block,
// 16 warps/SM (4/SMSP). bA/eta/tau live in per-lane smem slots (stride 31,
// conflict-free, no cross-lane access). x + transients stay in registers.
// Lane L (0..29) owns elements j = 10L..10L+9.
// ---------------------------------------------------------------------------
__global__ void __launch_bounds__(WARPS * 32, 1)
ladmm_main(const float* __restrict__ b, float* __restrict__ out) {
    extern __shared__ float sm[];
    float*  sA    = sm;                                   // NM*TBL        = 3744
    float*  sHn   = sA + NM * TBL;                        // 5*NM*TBL      = 18720
    float2* sct2  = (float2*)(sHn + NLAYERS * NM * TBL);  // 5*24 float2
    float*  sscal = (float*)(sct2 + NLAYERS * 24);        // 40
    float2* slots = (float2*)(sscal + 40);                // WARPS*WSLOT2 float2

    int tid = threadIdx.x;
    for (int i = tid; i < NM * TBL; i += WARPS * 32) sA[i] = g_At[i];
    for (int i = tid; i < NLAYERS * NM * TBL; i += WARPS * 32) sHn[i] = (&g_Hn[0][0])[i];
    for (int i = tid; i < NLAYERS * 24; i += WARPS * 32) {
        float v = (&g_ct[0][0])[i];
        sct2[i] = make_float2(v, v);
    }
    for (int i = tid; i < NLAYERS * 8; i += WARPS * 32) sscal[i] = (&g_scal[0][0])[i];
    __syncthreads();

    int wid = tid >> 5, lane = tid & 31;
    int base13 = lane * 13;
    int j0 = lane * 10;
    int lm1 = (lane + 29) % 30;
    int lp1 = (lane + 1) % 30;

    const float2 neg1 = make_float2(-1.f, -1.f);
    const float2 zero2 = make_float2(0.f, 0.f);
    // per-lane private slots: [0..9]=bA, [10..19]=eta, [20..29]=tau
    float2* mybA  = slots + wid * WSLOT2 + lane * LSTRIDE;
    float2* myeta = mybA + 10;
    float2* mytau = mybA + 20;

    #pragma unroll 1
    for (int rit = 0; rit < RPW; rit++) {
        int pairIdx = blockIdx.x * (WARPS * RPW) + wid * RPW + rit;
        size_t row0 = (size_t)pairIdx * 2;

        // --- b rows -> bm[m] packed pairs
        float bv = (lane < 2 * NM) ? b[(size_t)pairIdx * (2 * NM) + lane] : 0.f;
        float2 bm[9];
        #pragma unroll
        for (int m = 0; m < 9; m++)
            bm[m] = make_float2(__shfl_sync(FULLMASK, bv, m),
                                __shfl_sync(FULLMASK, bv, 9 + m));

        // --- bA[t] = sum_m bm[m]*A[m][j0+t] -> smem slots; init eta/tau = 0
        #pragma unroll
        for (int t = 0; t < 10; t++) {
            float2 acc = f2mul(bm[0], dup(sA[0 * TBL + base13 + t]));
            #pragma unroll
            for (int m = 1; m < 9; m++)
                acc = f2fma(bm[m], dup(sA[m * TBL + base13 + t]), acc);
            mybA[t] = acc;
            myeta[t] = zero2;
            mytau[t] = zero2;
        }

        float2 x[10];
        #pragma unroll
        for (int t = 0; t < 10; t++) x[t] = make_float2(1.f, 1.f);

        #pragma unroll 1
        for (int l = 0; l < NLAYERS; l++) {
            const float* sc = sscal + l * 8;
            float gs = sc[0], als = sc[1], lamg = sc[2], invgs = sc[3], invals = sc[4];
            float2 g2 = dup(gs), al2 = dup(als), invg2 = dup(invgs), inval2 = dup(invals);
            const float2* ctab = sct2 + l * 24;
            const float* sHl = sHn + l * (NM * TBL);

            // --- residual r = bA + al*w - tau + g*u - eta
            float2 xm1 = shfl2(x[9], lm1);
            float2 r[10];
            #pragma unroll
            for (int t = 0; t < 10; t++) {
                float2 et = myeta[t];
                float2 ta = mytau[t];
                float2 xp = (t == 0) ? xm1 : x[t - 1];
                float2 v = f2fma(neg1, x[t], xp);
                v = f2fma(et, invg2, v);
                float2 u; u.x = softt(v.x, lamg); u.y = softt(v.y, lamg);
                float2 w = f2fma(ta, inval2, x[t]);
                w.x = fmaxf(w.x, 0.f); w.y = fmaxf(w.y, 0.f);
                float2 s = f2fma(neg1, ta, mybA[t]);
                s = f2fma(al2, w, s);
                s = f2fma(g2, u, s);
                r[t] = f2fma(neg1, et, s);
            }

            // --- y = C^-1 r : 21-tap circulant conv
            float2 y[10];
            float2 wchunk[10];
            #pragma unroll
            for (int k = 0; k < 10; k++) wchunk[k] = shfl2(r[k], lm1);
            {
                float2 c0 = ctab[0];
                #pragma unroll
                for (int t = 0; t < 10; t++) y[t] = f2mul(c0, wchunk[t]);
            }
            #pragma unroll
            for (int d = 1; d < 10; d++) {
                float2 cd = ctab[d];
                #pragma unroll
                for (int t = 0; t < 10; t++)
                    if (t + d < 10) y[t] = f2fma(cd, wchunk[t + d], y[t]);
            }
            #pragma unroll
            for (int i = 1; i < 20; i++) {
                float2 ci = ctab[i];
                #pragma unroll
                for (int t = 0; t < 10; t++) {
                    int k = t + i - 10;
                    if (k >= 0 && k < 10) y[t] = f2fma(ci, r[k], y[t]);
                }
            }
            #pragma unroll
            for (int k = 0; k < 10; k++) wchunk[k] = shfl2(r[k], lp1);
            #pragma unroll
            for (int i = 11; i < 21; i++) {
                float2 ci = ctab[i];
                #pragma unroll
                for (int t = 0; t < 10; t++) {
                    int k = t + i - 20;
                    if (k >= 0 && k < 10) y[t] = f2fma(ci, wchunk[k], y[t]);
                }
            }

            // --- pd[m] = sum_j y_j A[m][j]
            float2 pd[9];
            #pragma unroll
            for (int m = 0; m < 9; m++)
                pd[m] = f2mul(y[0], dup(sA[m * TBL + base13 + 0]));
            #pragma unroll
            for (int t = 1; t < 10; t++) {
                #pragma unroll
                for (int m = 0; m < 9; m++)
                    pd[m] = f2fma(y[t], dup(sA[m * TBL + base13 + t]), pd[m]);
            }
            #pragma unroll
            for (int m = 0; m < 9; m++) pd[m] = bfly_sum(pd[m]);

            // --- xn = y + sum_m pd[m] * Hn[m][j]  (overwrite r: dead)
            float2 xn[10];
            #pragma unroll
            for (int t = 0; t < 10; t++) {
                float2 acc = y[t];
                #pragma unroll
                for (int m = 0; m < 9; m++)
                    acc = f2fma(pd[m], dup(sHl[m * TBL + base13 + t]), acc);
                xn[t] = acc;
            }

            // --- dual updates (recompute u,w from OLD state)
            float2 xnm1 = shfl2(xn[9], lm1);
            float2 xprev_old = xm1;
            #pragma unroll
            for (int t = 0; t < 10; t++) {
                float2 et = myeta[t];
                float2 ta = mytau[t];
                float2 xp = xprev_old;
                xprev_old = x[t];
                float2 xnp = (t == 0) ? xnm1 : xn[t - 1];
                float2 v = f2fma(neg1, x[t], xp);
                v = f2fma(et, invg2, v);
                float2 u; u.x = softt(v.x, lamg); u.y = softt(v.y, lamg);
                float2 w = f2fma(ta, inval2, x[t]);
                w.x = fmaxf(w.x, 0.f); w.y = fmaxf(w.y, 0.f);
                float2 d1 = f2fma(neg1, xn[t], xnp);
                d1 = f2fma(neg1, u, d1);
                myeta[t] = f2fma(g2, d1, et);
                float2 d2 = f2fma(neg1, w, xn[t]);
                mytau[t] = f2fma(al2, d2, ta);
                x[t] = xn[t];
            }
        }

        // --- store: reuse this warp's slot region as staging (state dead now)
        float* wstage = (float*)(slots + wid * WSLOT2);  // 1984 floats avail
        __syncwarp();
        if (lane < 30) {
            #pragma unroll
            for (int t = 0; t < 10; t++) {
                wstage[j0 + t]       = x[t].x;
                wstage[304 + j0 + t] = x[t].y;
            }
        }
        __syncwarp();
        {
            const float4* st4 = reinterpret_cast<const float4*>(wstage);
            float4* out4 = reinterpret_cast<float4*>(out);
            size_t o0 = row0 * (N / 4);
            for (int idx = lane; idx < N / 4; idx += 32) {
                out4[o0 + idx] = st4[idx];
                out4[o0 + N / 4 + idx] = st4[76 + idx];
            }
        }
        __syncwarp();
    }
}

// ---------------------------------------------------------------------------
extern "C" void kernel_launch(void* const* d_in, const int* in_sizes, int n_in,
                              void* d_out, int out_size) {
    const float* b         = (const float*)d_in[0];
    const float* A         = (const float*)d_in[2];
    const float* gamma_tv  = (const float*)d_in[3];
    const float* lambda_tv = (const float*)d_in[4];
    const float* alpha     = (const float*)d_in[5];
    float* out = (float*)d_out;

    pre_A_kernel<<<(NM * TBL + 255) / 256, 256>>>(A);
    pre_layer_kernel<<<NLAYERS, 256>>>(A, gamma_tv, lambda_tv, alpha);

    size_t smembytes = (size_t)(NM * TBL * (1 + NLAYERS)              // 22464
                                + NLAYERS * 24 * 2 + NLAYERS * 8      // 280
                                + (size_t)WARPS * WSLOT2 * 2)         // 31744
                       * sizeof(float);                               // ~213KB
    cudaFuncSetAttribute(ladmm_main,
                         cudaFuncAttributeMaxDynamicSharedMemorySize,
                         (int)smembytes);
    int grid = BATCH / (2 * WARPS * RPW);
    ladmm_main<<<grid, WARPS * 32, smembytes>>>(b, out);
}

// round 7
// speedup vs baseline: 1.2637x; 1.2637x over previous
#include <cuda_runtime.h>
#include <math.h>

#define N       300
#define NM      9
#define BATCH   131072
#define NLAYERS 5
#define KTAP    10
#define TAPS    (2*KTAP + 1)   // 21
#define TBL12   384            // stride-12 table: row m occupies [m*384 + lane*12 + t]
#define WARPS   8
#define RPW     8              // row-PAIRS per warp
#define FULLMASK 0xffffffffu

static __device__ double g_cfull[NLAYERS][N];
static __device__ float  g_G[NLAYERS][NM * N];
static __device__ float  g_At[NM * TBL12];           // A[m][j], j=10L+t at [m*384+12L+t]
static __device__ float  g_Hn[NLAYERS][NM * TBL12];  // NEGATED H, same layout
static __device__ float  g_ct[NLAYERS][24];          // conv taps ct[i]=c[|i-10|]
static __device__ float  g_scal[NLAYERS][8];

// ---------------------------------------------------------------------------
// packed f32x2 + warp helpers (sm_103a)
// ---------------------------------------------------------------------------
__device__ __forceinline__ float2 f2fma(float2 a, float2 b, float2 c) {
    unsigned long long ra = reinterpret_cast<unsigned long long&>(a);
    unsigned long long rb = reinterpret_cast<unsigned long long&>(b);
    unsigned long long rc = reinterpret_cast<unsigned long long&>(c);
    unsigned long long rd;
    asm("fma.rn.f32x2 %0, %1, %2, %3;" : "=l"(rd) : "l"(ra), "l"(rb), "l"(rc));
    return reinterpret_cast<float2&>(rd);
}
__device__ __forceinline__ float2 f2add(float2 a, float2 b) {
    unsigned long long ra = reinterpret_cast<unsigned long long&>(a);
    unsigned long long rb = reinterpret_cast<unsigned long long&>(b);
    unsigned long long rd;
    asm("add.rn.f32x2 %0, %1, %2;" : "=l"(rd) : "l"(ra), "l"(rb));
    return reinterpret_cast<float2&>(rd);
}
__device__ __forceinline__ float2 f2mul(float2 a, float2 b) {
    unsigned long long ra = reinterpret_cast<unsigned long long&>(a);
    unsigned long long rb = reinterpret_cast<unsigned long long&>(b);
    unsigned long long rd;
    asm("mul.rn.f32x2 %0, %1, %2;" : "=l"(rd) : "l"(ra), "l"(rb));
    return reinterpret_cast<float2&>(rd);
}
__device__ __forceinline__ float2 dup(float s) { return make_float2(s, s); }
__device__ __forceinline__ float2 shfl2(float2 v, int src) {
    float2 r;
    r.x = __shfl_sync(FULLMASK, v.x, src);
    r.y = __shfl_sync(FULLMASK, v.y, src);
    return r;
}
__device__ __forceinline__ float2 bfly_sum(float2 v) {
    #pragma unroll
    for (int off = 16; off >= 1; off >>= 1) {
        float sx = __shfl_xor_sync(FULLMASK, v.x, off);
        float sy = __shfl_xor_sync(FULLMASK, v.y, off);
        v = f2add(v, make_float2(sx, sy));
    }
    return v;
}
__device__ __forceinline__ float softt(float v, float lam) {
    return copysignf(fmaxf(fabsf(v) - lam, 0.f), v);
}

// ---------------------------------------------------------------------------
__global__ void pre_A_kernel(const float* __restrict__ A) {
    int idx = blockIdx.x * blockDim.x + threadIdx.x;
    if (idx < NM * TBL12) {
        int m = idx / TBL12, ii = idx % TBL12;
        int L = ii / 12, t = ii % 12;
        int j = L * 10 + t;
        g_At[idx] = (t < 10 && j < N) ? A[m * N + j] : 0.0f;
    }
}

// ---------------------------------------------------------------------------
__global__ void pre_layer_kernel(const float* __restrict__ A,
                                 const float* __restrict__ gamma_tv,
                                 const float* __restrict__ lambda_tv,
                                 const float* __restrict__ alpha) {
    const double PI = 3.14159265358979323846;
    int l = blockIdx.x;
    int tid = threadIdx.x;
    double g = (double)gamma_tv[l], al = (double)alpha[l];

    __shared__ double costab[N];
    __shared__ double invlam[N];
    for (int m = tid; m < N; m += blockDim.x) {
        double th = 2.0 * PI * (double)m / (double)N;
        costab[m] = cos(th);
        invlam[m] = 1.0 / (al + 2.0 * g - 2.0 * g * costab[m]);
    }
    __syncthreads();

    for (int k = tid; k < N; k += blockDim.x) {
        double s = 0.0;
        int mk = 0;
        for (int m = 0; m < N; m++) {
            s += costab[mk] * invlam[m];
            mk += k; if (mk >= N) mk -= N;
        }
        g_cfull[l][k] = s / (double)N;
    }
    __syncthreads();

    for (int idx = tid; idx < NM * N; idx += blockDim.x) {
        int m = idx / N, j = idx % N;
        float s = 0.f;
        for (int t = 0; t < N; t++) {
            int d = j - t; if (d < 0) d += N;
            s += A[m * N + t] * (float)g_cfull[l][d];
        }
        g_G[l][m * N + j] = s;
    }
    __syncthreads();

    __shared__ double S9[81], S9i[81];
    for (int idx = tid; idx < 81; idx += blockDim.x) {
        int p = idx / 9, q = idx % 9;
        double s = (p == q) ? 1.0 : 0.0;
        for (int j = 0; j < N; j++)
            s += (double)g_G[l][p * N + j] * (double)A[q * N + j];
        S9[idx] = s;
    }
    __syncthreads();

    if (tid == 0) {
        for (int i = 0; i < 81; i++) S9i[i] = ((i / 9) == (i % 9)) ? 1.0 : 0.0;
        for (int col = 0; col < 9; col++) {
            int piv = col; double best = fabs(S9[col * 9 + col]);
            for (int rr = col + 1; rr < 9; rr++) {
                double v = fabs(S9[rr * 9 + col]);
                if (v > best) { best = v; piv = rr; }
            }
            if (piv != col) {
                for (int c2 = 0; c2 < 9; c2++) {
                    double tmp = S9[col * 9 + c2]; S9[col * 9 + c2] = S9[piv * 9 + c2]; S9[piv * 9 + c2] = tmp;
                    tmp = S9i[col * 9 + c2]; S9i[col * 9 + c2] = S9i[piv * 9 + c2]; S9i[piv * 9 + c2] = tmp;
                }
            }
            double d = 1.0 / S9[col * 9 + col];
            for (int c2 = 0; c2 < 9; c2++) { S9[col * 9 + c2] *= d; S9i[col * 9 + c2] *= d; }
            for (int rr = 0; rr < 9; rr++) {
                if (rr == col) continue;
                double f = S9[rr * 9 + col];
                for (int c2 = 0; c2 < 9; c2++) {
                    S9[rr * 9 + c2]  -= f * S9[col * 9 + c2];
                    S9i[rr * 9 + c2] -= f * S9i[col * 9 + c2];
                }
            }
        }
    }
    __syncthreads();

    for (int idx = tid; idx < NM * TBL12; idx += blockDim.x) {
        int m = idx / TBL12, ii = idx % TBL12;
        int L = ii / 12, t = ii % 12;
        int j = L * 10 + t;
        float s = 0.f;
        if (t < 10 && j < N) {
            for (int q = 0; q < NM; q++)
                s -= (float)S9i[m * 9 + q] * g_G[l][q * N + j];
        }
        g_Hn[l][idx] = s;
    }
    for (int i = tid; i < 24; i += blockDim.x) {
        float v = 0.f;
        if (i < TAPS) { int d = i - KTAP; if (d < 0) d = -d; v = (float)g_cfull[l][d]; }
        g_ct[l][i] = v;
    }
    if (tid == 0) {
        g_scal[l][0] = (float)g;
        g_scal[l][1] = (float)al;
        g_scal[l][2] = (float)((double)lambda_tv[l] / g);
        g_scal[l][3] = (float)(1.0 / g);
        g_scal[l][4] = (float)(1.0 / al);
    }
}

// ---------------------------------------------------------------------------
// Main fused kernel (R2 config: state in registers, 8 warps, 1 block/SM).
// Tables in stride-12 layout -> 3x LDS.128 per row, conflict-free.
// Reductions via butterfly shuffles (identical math to the 899us baseline).
// Lane L (0..29) owns elements j = 10L..10L+9.
// ---------------------------------------------------------------------------
__global__ void __launch_bounds__(WARPS * 32)
ladmm_main(const float* __restrict__ b, float* __restrict__ out) {
    extern __shared__ float sm[];
    float*  sA    = sm;                                   // NM*TBL12      = 3456
    float*  sHn   = sA + NM * TBL12;                      // 5*NM*TBL12    = 17280
    float2* sct2  = (float2*)(sHn + NLAYERS * NM * TBL12);// 5*24 float2
    float*  sscal = (float*)(sct2 + NLAYERS * 24);        // 40
    float*  stage = sscal + 40;                           // WARPS*608

    int tid = threadIdx.x;
    for (int i = tid; i < NM * TBL12; i += WARPS * 32) sA[i] = g_At[i];
    for (int i = tid; i < NLAYERS * NM * TBL12; i += WARPS * 32) sHn[i] = (&g_Hn[0][0])[i];
    for (int i = tid; i < NLAYERS * 24; i += WARPS * 32) {
        float v = (&g_ct[0][0])[i];
        sct2[i] = make_float2(v, v);
    }
    for (int i = tid; i < NLAYERS * 8; i += WARPS * 32) sscal[i] = (&g_scal[0][0])[i];
    __syncthreads();

    int wid = tid >> 5, lane = tid & 31;
    int base12 = lane * 12;
    int j0 = lane * 10;
    int lm1 = (lane + 29) % 30;
    int lp1 = (lane + 1) % 30;

    const float2 neg1 = make_float2(-1.f, -1.f);
    float* wstage = stage + wid * 608;

    #pragma unroll 1
    for (int rit = 0; rit < RPW; rit++) {
        int pairIdx = blockIdx.x * (WARPS * RPW) + wid * RPW + rit;
        size_t row0 = (size_t)pairIdx * 2;

        // --- b rows -> bm[m] packed pairs
        float bv = (lane < 2 * NM) ? b[(size_t)pairIdx * (2 * NM) + lane] : 0.f;
        float2 bm[9];
        #pragma unroll
        for (int m = 0; m < 9; m++)
            bm[m] = make_float2(__shfl_sync(FULLMASK, bv, m),
                                __shfl_sync(FULLMASK, bv, 9 + m));

        // --- bA[t] = sum_m bm[m]*A[m][j0+t]  (m-outer, vector row loads)
        float2 bA[10];
        #pragma unroll
        for (int t = 0; t < 10; t++) bA[t] = make_float2(0.f, 0.f);
        #pragma unroll
        for (int m = 0; m < 9; m++) {
            const float4* rA = reinterpret_cast<const float4*>(sA + m * TBL12 + base12);
            float4 q0 = rA[0], q1 = rA[1], q2 = rA[2];
            float av[10] = {q0.x,q0.y,q0.z,q0.w,q1.x,q1.y,q1.z,q1.w,q2.x,q2.y};
            #pragma unroll
            for (int t = 0; t < 10; t++)
                bA[t] = f2fma(bm[m], dup(av[t]), bA[t]);
        }

        float2 x[10], eta[10], tau[10];
        #pragma unroll
        for (int t = 0; t < 10; t++) {
            x[t] = make_float2(1.f, 1.f);
            eta[t] = make_float2(0.f, 0.f);
            tau[t] = make_float2(0.f, 0.f);
        }

        #pragma unroll 1
        for (int l = 0; l < NLAYERS; l++) {
            const float* sc = sscal + l * 8;
            float gs = sc[0], als = sc[1], lamg = sc[2], invgs = sc[3], invals = sc[4];
            float2 g2 = dup(gs), al2 = dup(als), invg2 = dup(invgs), inval2 = dup(invals);
            const float2* ctab = sct2 + l * 24;
            const float* sHl = sHn + l * (NM * TBL12);

            // --- residual r = bA + al*w - tau + g*u - eta
            float2 xm1 = shfl2(x[9], lm1);
            float2 r[10];
            #pragma unroll
            for (int t = 0; t < 10; t++) {
                float2 xp = (t == 0) ? xm1 : x[t - 1];
                float2 v = f2fma(neg1, x[t], xp);
                v = f2fma(eta[t], invg2, v);
                float2 u; u.x = softt(v.x, lamg); u.y = softt(v.y, lamg);
                float2 w = f2fma(tau[t], inval2, x[t]);
                w.x = fmaxf(w.x, 0.f); w.y = fmaxf(w.y, 0.f);
                float2 s = f2fma(neg1, tau[t], bA[t]);
                s = f2fma(al2, w, s);
                s = f2fma(g2, u, s);
                r[t] = f2fma(neg1, eta[t], s);
            }

            // --- y = C^-1 r : 21-tap circulant conv
            float2 y[10];
            float2 wchunk[10];
            #pragma unroll
            for (int k = 0; k < 10; k++) wchunk[k] = shfl2(r[k], lm1);
            {
                float2 c0 = ctab[0];
                #pragma unroll
                for (int t = 0; t < 10; t++) y[t] = f2mul(c0, wchunk[t]);
            }
            #pragma unroll
            for (int d = 1; d < 10; d++) {
                float2 cd = ctab[d];
                #pragma unroll
                for (int t = 0; t < 10; t++)
                    if (t + d < 10) y[t] = f2fma(cd, wchunk[t + d], y[t]);
            }
            #pragma unroll
            for (int i = 1; i < 20; i++) {
                float2 ci = ctab[i];
                #pragma unroll
                for (int t = 0; t < 10; t++) {
                    int k = t + i - 10;
                    if (k >= 0 && k < 10) y[t] = f2fma(ci, r[k], y[t]);
                }
            }
            #pragma unroll
            for (int k = 0; k < 10; k++) wchunk[k] = shfl2(r[k], lp1);
            #pragma unroll
            for (int i = 11; i < 21; i++) {
                float2 ci = ctab[i];
                #pragma unroll
                for (int t = 0; t < 10; t++) {
                    int k = t + i - 20;
                    if (k >= 0 && k < 10) y[t] = f2fma(ci, wchunk[k], y[t]);
                }
            }

            // --- pd[m] = sum_j y_j A[m][j]  (m-outer vector loads + butterfly)
            float2 pd[9];
            #pragma unroll
            for (int m = 0; m < 9; m++) {
                const float4* rA = reinterpret_cast<const float4*>(sA + m * TBL12 + base12);
                float4 q0 = rA[0], q1 = rA[1], q2 = rA[2];
                float av[10] = {q0.x,q0.y,q0.z,q0.w,q1.x,q1.y,q1.z,q1.w,q2.x,q2.y};
                float2 acc = f2mul(y[0], dup(av[0]));
                #pragma unroll
                for (int t = 1; t < 10; t++)
                    acc = f2fma(y[t], dup(av[t]), acc);
                pd[m] = acc;
            }
            #pragma unroll
            for (int m = 0; m < 9; m++) pd[m] = bfly_sum(pd[m]);

            // --- xn = y + sum_m pd[m] * Hn[m][j]  (m-outer vector loads)
            float2 xn[10];
            #pragma unroll
            for (int t = 0; t < 10; t++) xn[t] = y[t];
            #pragma unroll
            for (int m = 0; m < 9; m++) {
                const float4* rH = reinterpret_cast<const float4*>(sHl + m * TBL12 + base12);
                float4 q0 = rH[0], q1 = rH[1], q2 = rH[2];
                float hv[10] = {q0.x,q0.y,q0.z,q0.w,q1.x,q1.y,q1.z,q1.w,q2.x,q2.y};
                #pragma unroll
                for (int t = 0; t < 10; t++)
                    xn[t] = f2fma(pd[m], dup(hv[t]), xn[t]);
            }

            // --- dual updates (recompute u,w from OLD state)
            float2 xnm1 = shfl2(xn[9], lm1);
            float2 xprev_old = xm1;
            #pragma unroll
            for (int t = 0; t < 10; t++) {
                float2 xp = xprev_old;
                xprev_old = x[t];
                float2 xnp = (t == 0) ? xnm1 : xn[t - 1];
                float2 v = f2fma(neg1, x[t], xp);
                v = f2fma(eta[t], invg2, v);
                float2 u; u.x = softt(v.x, lamg); u.y = softt(v.y, lamg);
                float2 w = f2fma(tau[t], inval2, x[t]);
                w.x = fmaxf(w.x, 0.f); w.y = fmaxf(w.y, 0.f);
                float2 d1 = f2fma(neg1, xn[t], xnp);
                d1 = f2fma(neg1, u, d1);
                eta[t] = f2fma(g2, d1, eta[t]);
                float2 d2 = f2fma(neg1, w, xn[t]);
                tau[t] = f2fma(al2, d2, tau[t]);
                x[t] = xn[t];
            }
        }

        // --- store both rows, coalesced float4 via smem staging
        __syncwarp();
        if (lane < 30) {
            #pragma unroll
            for (int t = 0; t < 10; t++) {
                wstage[j0 + t]       = x[t].x;
                wstage[304 + j0 + t] = x[t].y;
            }
        }
        __syncwarp();
        {
            const float4* st4 = reinterpret_cast<const float4*>(wstage);
            float4* out4 = reinterpret_cast<float4*>(out);
            size_t o0 = row0 * (N / 4);
            for (int idx = lane; idx < N / 4; idx += 32) {
                out4[o0 + idx] = st4[idx];
                out4[o0 + N / 4 + idx] = st4[76 + idx];
            }
        }
        __syncwarp();
    }
}

// ---------------------------------------------------------------------------
extern "C" void kernel_launch(void* const* d_in, const int* in_sizes, int n_in,
                              void* d_out, int out_size) {
    const float* b         = (const float*)d_in[0];
    const float* A         = (const float*)d_in[2];
    const float* gamma_tv  = (const float*)d_in[3];
    const float* lambda_tv = (const float*)d_in[4];
    const float* alpha     = (const float*)d_in[5];
    float* out = (float*)d_out;

    pre_A_kernel<<<(NM * TBL12 + 255) / 256, 256>>>(A);
    pre_layer_kernel<<<NLAYERS, 256>>>(A, gamma_tv, lambda_tv, alpha);

    size_t smembytes = (size_t)(NM * TBL12 * (1 + NLAYERS)            // 20736
                                + NLAYERS * 24 * 2 + NLAYERS * 8      // 280
                                + WARPS * 608) * sizeof(float);       // 4864 -> ~103KB
    cudaFuncSetAttribute(ladmm_main,
                         cudaFuncAttributeMaxDynamicSharedMemorySize,
                         (int)smembytes);
    int grid = BATCH / (2 * WARPS * RPW);
    ladmm_main<<<grid, WARPS * 32, smembytes>>>(b, out);
}